// round 9
// baseline (speedup 1.0000x reference)
#include <cuda_runtime.h>
#include <cuda_fp16.h>
#include <cstdint>

// NearestEmbed via mma.sync (HMMA) fp16 2-split GEMM + fused argmin.
// R9: A fragments register-resident across the whole stage loop (LDSM once),
//     stage loop only streams B. Arithmetic identical to R8 (rel_err 0.0).
//   xe = x.w via 3 fp16 mma combos (x0w0, x0w1, x1w0), fp32 accum.
//   w scaled by 1024 (exact) before split; epilogue multiplies by -2/1024 (exact).
//   x2/e2: sequential fadd(rn(v*v)) ascending d; first-index tie-break.

#define DCH 128
#define KCODES 1024
#define HW 4096
#define BATCH 32
#define RES_ELEMS ((size_t)BATCH * DCH * HW)

#define NTHREADS 512
#define MTILE 128            // pixels per CTA
#define NSTAGE 64            // codes per stage
#define NSTAGES 16

#define A_SPLIT 32768        // one fp16 split of x tile: 8 chunks x 128px x 32B
#define W_SPLIT 16384        // one fp16 split of w stage: 8 chunks x 64c x 32B
#define W_STAGE (2 * W_SPLIT)   // 32768

#define OFF_A    0           // 2 x A_SPLIT = 65536
#define OFF_W    65536       // ring: 3 x W_STAGE = 98304
#define OFF_XF   65536       // overlay: x f32 tile (65536) inside ring, pre-loop
#define OFF_E2   163840      // 1024 f32
#define OFF_X2   167936      // 128 f32
#define OFF_BEST 168448      // 128 u64
#define SMEM_TOTAL 169472

__device__ __align__(16) unsigned char g_wsplit[NSTAGES * W_STAGE];
__device__ float g_e2[KCODES];

// ---------------- helpers ----------------
__device__ __forceinline__ uint32_t smem_u32(const void* p) {
    uint32_t a;
    asm("{ .reg .u64 t; cvta.to.shared.u64 t, %1; cvt.u32.u64 %0, t; }" : "=r"(a) : "l"(p));
    return a;
}
__device__ __forceinline__ void cp16(uint32_t dst, const void* src) {
    asm volatile("cp.async.cg.shared.global [%0], [%1], 16;" :: "r"(dst), "l"(src) : "memory");
}
#define CP_COMMIT() asm volatile("cp.async.commit_group;" ::: "memory")
#define CP_WAIT(N)  asm volatile("cp.async.wait_group %0;" :: "n"(N) : "memory")

#define LDSM_X4(R0, R1, R2, R3, ADDR) \
    asm volatile("ldmatrix.sync.aligned.m8n8.x4.shared.b16 {%0,%1,%2,%3}, [%4];" \
        : "=r"(R0), "=r"(R1), "=r"(R2), "=r"(R3) : "r"(ADDR))

#define MMA16816(D, A, B0, B1) \
    asm volatile("mma.sync.aligned.m16n8k16.row.col.f32.f16.f16.f32 " \
        "{%0,%1,%2,%3}, {%4,%5,%6,%7}, {%8,%9}, {%0,%1,%2,%3};" \
        : "+f"((D)[0]), "+f"((D)[1]), "+f"((D)[2]), "+f"((D)[3]) \
        : "r"((A)[0]), "r"((A)[1]), "r"((A)[2]), "r"((A)[3]), "r"(B0), "r"(B1))

// XOR-swizzled granule offset: row p (4 px/codes per 128B row), k-half h.
__device__ __host__ __forceinline__ uint32_t swz16(uint32_t p, uint32_t h) {
    uint32_t r = p >> 2;
    uint32_t col = (((p & 3u) * 2u + h) ^ (r & 7u));
    return r * 128u + col * 16u;
}

// exact fp32 -> fp16 hi/lo split (residual subtraction is exact: <=13 sig bits)
__device__ __forceinline__ void split2(float v, unsigned short& s0, unsigned short& s1) {
    __half h0 = __float2half_rn(v);
    float r = v - __half2float(h0);
    __half h1 = __float2half_rn(r);
    s0 = __half_as_ushort(h0);
    s1 = __half_as_ushort(h1);
}
__device__ __forceinline__ uint4 pack8(const unsigned short* s) {
    uint4 v;
    v.x = (uint32_t)s[0] | ((uint32_t)s[1] << 16);
    v.y = (uint32_t)s[2] | ((uint32_t)s[3] << 16);
    v.z = (uint32_t)s[4] | ((uint32_t)s[5] << 16);
    v.w = (uint32_t)s[6] | ((uint32_t)s[7] << 16);
    return v;
}

// ---------------- prep: e2 (exact) + scaled fp16 2-splits of w ----------------
__global__ void convert_w_kernel(const float* __restrict__ w) {
    const int nt = blockIdx.x;        // stage (64 codes)
    const int c = threadIdx.x;        // local code 0..63
    const int k = nt * NSTAGE + c;
    float e2 = 0.0f;
    for (int g = 0; g < 16; ++g) {    // granule g: d = 8g..8g+7 ascending
        unsigned short s0[8], s1[8];
#pragma unroll
        for (int j = 0; j < 8; ++j) {
            float v = w[(size_t)(g * 8 + j) * KCODES + k];
            e2 = __fadd_rn(e2, __fmul_rn(v, v));
            split2(v * 1024.0f, s0[j], s1[j]);   // exact scale by 2^10
        }
        const int ch = g >> 1, h = g & 1;
        unsigned char* base = g_wsplit + (size_t)nt * W_STAGE + (size_t)ch * 2048
                            + swz16((uint32_t)c, (uint32_t)h);
        *(uint4*)(base + 0 * W_SPLIT) = pack8(s0);
        *(uint4*)(base + 1 * W_SPLIT) = pack8(s1);
    }
    g_e2[k] = e2;
}

// ---------------- main ----------------
__global__ __launch_bounds__(NTHREADS, 1)
void nearest_embed_hmma_kernel(const float* __restrict__ x,
                               const float* __restrict__ w,
                               float* __restrict__ out,
                               int write_amin) {
    extern __shared__ char smem[];
    const uint32_t su = smem_u32(smem);
    const int tid = threadIdx.x;
    const int blk = blockIdx.x;
    const int b = blk >> 5;
    const int hw0 = (blk & 31) * MTILE;

    float* e2s = (float*)(smem + OFF_E2);
    float* x2s = (float*)(smem + OFF_X2);
    unsigned long long* best = (unsigned long long*)(smem + OFF_BEST);

    if (tid < MTILE) best[tid] = 0xFFFFFFFFFFFFFFFFull;
    for (int i = tid; i < KCODES; i += NTHREADS) e2s[i] = g_e2[i];

    // ---- stage x f32 tile [128d][128px] into OFF_XF ----
    const float* xbase = x + ((size_t)b * DCH) * HW + hw0;
    for (int t = tid; t < DCH * 32; t += NTHREADS) {
        int d = t >> 5, q = t & 31;
        cp16(su + OFF_XF + (uint32_t)(d * 512 + q * 16),
             xbase + (size_t)d * HW + q * 4);
    }
    CP_COMMIT();
    CP_WAIT(0);
    __syncthreads();

    // ---- x2 (exact sequential ascending d) ----
    const float* xf = (const float*)(smem + OFF_XF);
    if (tid < MTILE) {
        float a = 0.0f;
        for (int d = 0; d < DCH; ++d) {
            float v = xf[d * MTILE + tid];
            a = __fadd_rn(a, __fmul_rn(v, v));
        }
        x2s[tid] = a;
    }

    // ---- convert x tile -> 2 fp16 splits (swizzled A layout) ----
    {
        const int px = tid & 127;
        const int quarter = tid >> 7;        // 0..3 -> 4 granules each
        for (int g = quarter * 4; g < quarter * 4 + 4; ++g) {
            unsigned short s0[8], s1[8];
#pragma unroll
            for (int j = 0; j < 8; ++j)
                split2(xf[(g * 8 + j) * MTILE + px], s0[j], s1[j]);
            const int ch = g >> 1, h = g & 1;
            const uint32_t off = (uint32_t)(ch * 4096) + swz16((uint32_t)px, (uint32_t)h);
            *(uint4*)(smem + OFF_A + 0 * A_SPLIT + off) = pack8(s0);
            *(uint4*)(smem + OFF_A + 1 * A_SPLIT + off) = pack8(s1);
        }
    }
    __syncthreads();   // A ready; XF area (ring slots 0-1) now reusable

    // ---- prefetch w stages 0 and 1 ----
    for (int s = 0; s < 2; ++s) {
        const unsigned char* src = g_wsplit + (size_t)s * W_STAGE;
        const uint32_t dst = su + OFF_W + s * W_STAGE;
        for (int t = tid; t < W_STAGE / 16; t += NTHREADS)
            cp16(dst + (uint32_t)(t * 16), src + (size_t)t * 16);
        CP_COMMIT();
    }

    // ---- per-thread fragment addressing ----
    const int lane = tid & 31;
    const int warp = tid >> 5;          // 16 warps: 8 px-groups x 2 code-halves
    const int pg = warp >> 1;
    const int chalf = warp & 1;
    const int px0 = pg * 16;

    const uint32_t ap = (uint32_t)(px0 + (lane & 7) + ((lane >> 3) & 1) * 8);
    const uint32_t ah = (uint32_t)(lane >> 4);
    const uint32_t aoff = swz16(ap, ah);
    const uint32_t bc = (uint32_t)((lane & 7) + ((lane >> 4) & 1) * 8);
    const uint32_t bh = (uint32_t)((lane >> 3) & 1);
    uint32_t boff[2];
#pragma unroll
    for (int ct = 0; ct < 2; ++ct)
        boff[ct] = swz16((uint32_t)(chalf * 32 + ct * 16) + bc, bh);

    // ---- hoist ALL A fragments into registers (once, reused all 16 stages) ----
    uint32_t Ar[8][8];    // [chunk][split*4 + reg]
#pragma unroll
    for (int ch = 0; ch < 8; ++ch) {
        LDSM_X4(Ar[ch][0], Ar[ch][1], Ar[ch][2], Ar[ch][3],
                su + OFF_A + 0 * A_SPLIT + ch * 4096 + aoff);
        LDSM_X4(Ar[ch][4], Ar[ch][5], Ar[ch][6], Ar[ch][7],
                su + OFF_A + 1 * A_SPLIT + ch * 4096 + aoff);
    }

    const float x2a = x2s[px0 + (lane >> 2)];
    const float x2b = x2s[px0 + 8 + (lane >> 2)];

    float acc[4][4];
#pragma unroll
    for (int t = 0; t < 4; ++t)
#pragma unroll
        for (int q = 0; q < 4; ++q) acc[t][q] = 0.0f;

    float bdA = __int_as_float(0x7F800000), bdB = bdA;
    int bkA = 0, bkB = 0;

    for (int nt = 0; nt < NSTAGES; ++nt) {
        __syncthreads();   // prev stage fully consumed -> ring slot (nt+2)%3 free

        if (nt + 2 < NSTAGES) {
            const unsigned char* src = g_wsplit + (size_t)(nt + 2) * W_STAGE;
            const uint32_t dst = su + OFF_W + ((nt + 2) % 3) * W_STAGE;
            for (int t = tid; t < W_STAGE / 16; t += NTHREADS)
                cp16(dst + (uint32_t)(t * 16), src + (size_t)t * 16);
            CP_COMMIT();
            CP_WAIT(2);
        } else if (nt == NSTAGES - 2) {
            CP_WAIT(1);
        } else {
            CP_WAIT(0);
        }
        __syncthreads();   // stage nt visible to all threads

        const uint32_t wb = su + OFF_W + (nt % 3) * W_STAGE;

#pragma unroll 1
        for (int ch = 0; ch < 8; ++ch) {
            const uint32_t* A0 = &Ar[ch][0];
            const uint32_t* A1 = &Ar[ch][4];
            // stream B: 4 independent LDSM.x4, then 12 MMA on 4 acc chains
            uint32_t p0, p1, p2, p3;       // ct0, w0 split
            uint32_t q0, q1, q2, q3;       // ct0, w1 split
            uint32_t r0, r1, r2, r3;       // ct1, w0 split
            uint32_t s0, s1, s2, s3;       // ct1, w1 split
            LDSM_X4(p0, p1, p2, p3, wb + 0 * W_SPLIT + ch * 2048 + boff[0]);
            LDSM_X4(q0, q1, q2, q3, wb + 1 * W_SPLIT + ch * 2048 + boff[0]);
            LDSM_X4(r0, r1, r2, r3, wb + 0 * W_SPLIT + ch * 2048 + boff[1]);
            LDSM_X4(s0, s1, s2, s3, wb + 1 * W_SPLIT + ch * 2048 + boff[1]);
            MMA16816(acc[0], A0, p0, p1);
            MMA16816(acc[1], A0, p2, p3);
            MMA16816(acc[2], A0, r0, r1);
            MMA16816(acc[3], A0, r2, r3);
            MMA16816(acc[0], A1, p0, p1);
            MMA16816(acc[1], A1, p2, p3);
            MMA16816(acc[2], A1, r0, r1);
            MMA16816(acc[3], A1, r2, r3);
            MMA16816(acc[0], A0, q0, q1);
            MMA16816(acc[1], A0, q2, q3);
            MMA16816(acc[2], A0, s0, s1);
            MMA16816(acc[3], A0, s2, s3);
        }

        // ---- stage epilogue: d2 + running argmin (ascending k) ----
        const int kq = nt * NSTAGE + chalf * 32 + (lane & 3) * 2;
#pragma unroll
        for (int t = 0; t < 4; ++t) {
            const int k0 = kq + t * 8;
#pragma unroll
            for (int q = 0; q < 2; ++q) {
                const int kk = k0 + q;
                const float e2v = e2s[kk];
                // acc holds xe*1024; -2*xe == (-2/1024)*acc, both scalings exact
                float tA = __fadd_rn(x2a, __fmul_rn(-0.001953125f, acc[t][q]));
                float dA = __fadd_rn(tA, e2v);
                if (dA < bdA) { bdA = dA; bkA = kk; }
                float tB = __fadd_rn(x2b, __fmul_rn(-0.001953125f, acc[t][q + 2]));
                float dB = __fadd_rn(tB, e2v);
                if (dB < bdB) { bdB = dB; bkB = kk; }
                acc[t][q] = 0.0f;
                acc[t][q + 2] = 0.0f;
            }
        }
    }

    // ---- merge across lanes/warps sharing a pixel ----
    {
        unsigned long long pA =
            ((unsigned long long)__float_as_uint(bdA) << 32) | (unsigned)bkA;
        unsigned long long pB =
            ((unsigned long long)__float_as_uint(bdB) << 32) | (unsigned)bkB;
        atomicMin(&best[px0 + (lane >> 2)], pA);
        atomicMin(&best[px0 + 8 + (lane >> 2)], pB);
    }
    __syncthreads();

    // ---- outputs: gather codebook rows + argmin ----
    const size_t obase = ((size_t)b * DCH) * HW + hw0;
    for (int t = tid; t < DCH * MTILE; t += NTHREADS) {
        int d = t >> 7;
        int px = t & 127;
        unsigned k = (unsigned)(best[px] & 0xFFFFFFFFu);
        out[obase + (size_t)d * HW + px] = w[(size_t)d * KCODES + k];
    }
    if (write_amin && tid < MTILE) {
        unsigned k = (unsigned)(best[tid] & 0xFFFFFFFFu);
        out[RES_ELEMS + (size_t)b * HW + hw0 + tid] = (float)k;
    }
}

extern "C" void kernel_launch(void* const* d_in, const int* in_sizes, int n_in,
                              void* d_out, int out_size) {
    const float* x = (const float*)d_in[0];
    const float* w = (const float*)d_in[1];
    float* out = (float*)d_out;
    const int write_amin = ((size_t)out_size > RES_ELEMS) ? 1 : 0;

    cudaFuncSetAttribute(nearest_embed_hmma_kernel,
                         cudaFuncAttributeMaxDynamicSharedMemorySize, SMEM_TOTAL);

    convert_w_kernel<<<NSTAGES, NSTAGE>>>(w);
    nearest_embed_hmma_kernel<<<(BATCH * HW) / MTILE, NTHREADS, SMEM_TOTAL>>>(
        x, w, out, write_amin);
}

// round 10
// speedup vs baseline: 1.1690x; 1.1690x over previous
#include <cuda_runtime.h>
#include <cuda_fp16.h>
#include <cstdint>

// NearestEmbed via mma.sync (HMMA) fp16 2-split GEMM + fused argmin.
// R10: A fragments truly register-resident (chunk loop fully unrolled so all
//      indices are compile-time; R9's runtime-indexed array spilled to local).
//   xe = x.w via 3 fp16 mma combos (x0w0, x0w1, x1w0), fp32 accum.
//   w scaled by 1024 (exact) before split; epilogue multiplies by -2/1024 (exact).
//   x2/e2: sequential fadd(rn(v*v)) ascending d; first-index tie-break.

#define DCH 128
#define KCODES 1024
#define HW 4096
#define BATCH 32
#define RES_ELEMS ((size_t)BATCH * DCH * HW)

#define NTHREADS 512
#define MTILE 128            // pixels per CTA
#define NSTAGE 64            // codes per stage
#define NSTAGES 16

#define A_SPLIT 32768        // one fp16 split of x tile: 8 chunks x 128px x 32B
#define W_SPLIT 16384        // one fp16 split of w stage: 8 chunks x 64c x 32B
#define W_STAGE (2 * W_SPLIT)   // 32768

#define OFF_A    0           // 2 x A_SPLIT = 65536
#define OFF_W    65536       // ring: 3 x W_STAGE = 98304
#define OFF_XF   65536       // overlay: x f32 tile (65536) inside ring, pre-loop
#define OFF_E2   163840      // 1024 f32
#define OFF_X2   167936      // 128 f32
#define OFF_BEST 168448      // 128 u64
#define SMEM_TOTAL 169472

__device__ __align__(16) unsigned char g_wsplit[NSTAGES * W_STAGE];
__device__ float g_e2[KCODES];

// ---------------- helpers ----------------
__device__ __forceinline__ uint32_t smem_u32(const void* p) {
    uint32_t a;
    asm("{ .reg .u64 t; cvta.to.shared.u64 t, %1; cvt.u32.u64 %0, t; }" : "=r"(a) : "l"(p));
    return a;
}
__device__ __forceinline__ void cp16(uint32_t dst, const void* src) {
    asm volatile("cp.async.cg.shared.global [%0], [%1], 16;" :: "r"(dst), "l"(src) : "memory");
}
#define CP_COMMIT() asm volatile("cp.async.commit_group;" ::: "memory")
#define CP_WAIT(N)  asm volatile("cp.async.wait_group %0;" :: "n"(N) : "memory")

#define LDSM_X4(R0, R1, R2, R3, ADDR) \
    asm volatile("ldmatrix.sync.aligned.m8n8.x4.shared.b16 {%0,%1,%2,%3}, [%4];" \
        : "=r"(R0), "=r"(R1), "=r"(R2), "=r"(R3) : "r"(ADDR))

#define MMA16816(D, A0r, A1r, A2r, A3r, B0, B1) \
    asm volatile("mma.sync.aligned.m16n8k16.row.col.f32.f16.f16.f32 " \
        "{%0,%1,%2,%3}, {%4,%5,%6,%7}, {%8,%9}, {%0,%1,%2,%3};" \
        : "+f"((D)[0]), "+f"((D)[1]), "+f"((D)[2]), "+f"((D)[3]) \
        : "r"(A0r), "r"(A1r), "r"(A2r), "r"(A3r), "r"(B0), "r"(B1))

// XOR-swizzled granule offset: row p (4 px/codes per 128B row), k-half h.
__device__ __host__ __forceinline__ uint32_t swz16(uint32_t p, uint32_t h) {
    uint32_t r = p >> 2;
    uint32_t col = (((p & 3u) * 2u + h) ^ (r & 7u));
    return r * 128u + col * 16u;
}

// exact fp32 -> fp16 hi/lo split (residual subtraction is exact: <=13 sig bits)
__device__ __forceinline__ void split2(float v, unsigned short& s0, unsigned short& s1) {
    __half h0 = __float2half_rn(v);
    float r = v - __half2float(h0);
    __half h1 = __float2half_rn(r);
    s0 = __half_as_ushort(h0);
    s1 = __half_as_ushort(h1);
}
__device__ __forceinline__ uint4 pack8(const unsigned short* s) {
    uint4 v;
    v.x = (uint32_t)s[0] | ((uint32_t)s[1] << 16);
    v.y = (uint32_t)s[2] | ((uint32_t)s[3] << 16);
    v.z = (uint32_t)s[4] | ((uint32_t)s[5] << 16);
    v.w = (uint32_t)s[6] | ((uint32_t)s[7] << 16);
    return v;
}

// ---------------- prep: e2 (exact) + scaled fp16 2-splits of w ----------------
__global__ void convert_w_kernel(const float* __restrict__ w) {
    const int nt = blockIdx.x;        // stage (64 codes)
    const int c = threadIdx.x;        // local code 0..63
    const int k = nt * NSTAGE + c;
    float e2 = 0.0f;
    for (int g = 0; g < 16; ++g) {    // granule g: d = 8g..8g+7 ascending
        unsigned short s0[8], s1[8];
#pragma unroll
        for (int j = 0; j < 8; ++j) {
            float v = w[(size_t)(g * 8 + j) * KCODES + k];
            e2 = __fadd_rn(e2, __fmul_rn(v, v));
            split2(v * 1024.0f, s0[j], s1[j]);   // exact scale by 2^10
        }
        const int ch = g >> 1, h = g & 1;
        unsigned char* base = g_wsplit + (size_t)nt * W_STAGE + (size_t)ch * 2048
                            + swz16((uint32_t)c, (uint32_t)h);
        *(uint4*)(base + 0 * W_SPLIT) = pack8(s0);
        *(uint4*)(base + 1 * W_SPLIT) = pack8(s1);
    }
    g_e2[k] = e2;
}

// ---------------- main ----------------
__global__ __launch_bounds__(NTHREADS, 1)
void nearest_embed_hmma_kernel(const float* __restrict__ x,
                               const float* __restrict__ w,
                               float* __restrict__ out,
                               int write_amin) {
    extern __shared__ char smem[];
    const uint32_t su = smem_u32(smem);
    const int tid = threadIdx.x;
    const int blk = blockIdx.x;
    const int b = blk >> 5;
    const int hw0 = (blk & 31) * MTILE;

    float* e2s = (float*)(smem + OFF_E2);
    float* x2s = (float*)(smem + OFF_X2);
    unsigned long long* best = (unsigned long long*)(smem + OFF_BEST);

    if (tid < MTILE) best[tid] = 0xFFFFFFFFFFFFFFFFull;
    for (int i = tid; i < KCODES; i += NTHREADS) e2s[i] = g_e2[i];

    // ---- stage x f32 tile [128d][128px] into OFF_XF ----
    const float* xbase = x + ((size_t)b * DCH) * HW + hw0;
    for (int t = tid; t < DCH * 32; t += NTHREADS) {
        int d = t >> 5, q = t & 31;
        cp16(su + OFF_XF + (uint32_t)(d * 512 + q * 16),
             xbase + (size_t)d * HW + q * 4);
    }
    CP_COMMIT();
    CP_WAIT(0);
    __syncthreads();

    // ---- x2 (exact sequential ascending d) ----
    const float* xf = (const float*)(smem + OFF_XF);
    if (tid < MTILE) {
        float a = 0.0f;
        for (int d = 0; d < DCH; ++d) {
            float v = xf[d * MTILE + tid];
            a = __fadd_rn(a, __fmul_rn(v, v));
        }
        x2s[tid] = a;
    }

    // ---- convert x tile -> 2 fp16 splits (swizzled A layout) ----
    {
        const int px = tid & 127;
        const int quarter = tid >> 7;        // 0..3 -> 4 granules each
        for (int g = quarter * 4; g < quarter * 4 + 4; ++g) {
            unsigned short s0[8], s1[8];
#pragma unroll
            for (int j = 0; j < 8; ++j)
                split2(xf[(g * 8 + j) * MTILE + px], s0[j], s1[j]);
            const int ch = g >> 1, h = g & 1;
            const uint32_t off = (uint32_t)(ch * 4096) + swz16((uint32_t)px, (uint32_t)h);
            *(uint4*)(smem + OFF_A + 0 * A_SPLIT + off) = pack8(s0);
            *(uint4*)(smem + OFF_A + 1 * A_SPLIT + off) = pack8(s1);
        }
    }
    __syncthreads();   // A ready; XF area (ring slots 0-1) now reusable

    // ---- prefetch w stages 0 and 1 ----
    for (int s = 0; s < 2; ++s) {
        const unsigned char* src = g_wsplit + (size_t)s * W_STAGE;
        const uint32_t dst = su + OFF_W + s * W_STAGE;
        for (int t = tid; t < W_STAGE / 16; t += NTHREADS)
            cp16(dst + (uint32_t)(t * 16), src + (size_t)t * 16);
        CP_COMMIT();
    }

    // ---- per-thread fragment addressing ----
    const int lane = tid & 31;
    const int warp = tid >> 5;          // 16 warps: 8 px-groups x 2 code-halves
    const int pg = warp >> 1;
    const int chalf = warp & 1;
    const int px0 = pg * 16;

    const uint32_t ap = (uint32_t)(px0 + (lane & 7) + ((lane >> 3) & 1) * 8);
    const uint32_t ah = (uint32_t)(lane >> 4);
    const uint32_t aoff = swz16(ap, ah);
    const uint32_t bc = (uint32_t)((lane & 7) + ((lane >> 4) & 1) * 8);
    const uint32_t bh = (uint32_t)((lane >> 3) & 1);
    uint32_t boff[2];
#pragma unroll
    for (int ct = 0; ct < 2; ++ct)
        boff[ct] = swz16((uint32_t)(chalf * 32 + ct * 16) + bc, bh);

    // ---- hoist ALL A fragments into registers (compile-time indices only) ----
    uint32_t Ar[64];    // [chunk*8 + split*4 + reg]
#pragma unroll
    for (int ch = 0; ch < 8; ++ch) {
        LDSM_X4(Ar[ch * 8 + 0], Ar[ch * 8 + 1], Ar[ch * 8 + 2], Ar[ch * 8 + 3],
                su + OFF_A + 0 * A_SPLIT + ch * 4096 + aoff);
        LDSM_X4(Ar[ch * 8 + 4], Ar[ch * 8 + 5], Ar[ch * 8 + 6], Ar[ch * 8 + 7],
                su + OFF_A + 1 * A_SPLIT + ch * 4096 + aoff);
    }

    const float x2a = x2s[px0 + (lane >> 2)];
    const float x2b = x2s[px0 + 8 + (lane >> 2)];

    float acc[4][4];
#pragma unroll
    for (int t = 0; t < 4; ++t)
#pragma unroll
        for (int q = 0; q < 4; ++q) acc[t][q] = 0.0f;

    float bdA = __int_as_float(0x7F800000), bdB = bdA;
    int bkA = 0, bkB = 0;

    for (int nt = 0; nt < NSTAGES; ++nt) {
        __syncthreads();   // prev stage fully consumed -> ring slot (nt+2)%3 free

        if (nt + 2 < NSTAGES) {
            const unsigned char* src = g_wsplit + (size_t)(nt + 2) * W_STAGE;
            const uint32_t dst = su + OFF_W + ((nt + 2) % 3) * W_STAGE;
            for (int t = tid; t < W_STAGE / 16; t += NTHREADS)
                cp16(dst + (uint32_t)(t * 16), src + (size_t)t * 16);
            CP_COMMIT();
            CP_WAIT(2);
        } else if (nt == NSTAGES - 2) {
            CP_WAIT(1);
        } else {
            CP_WAIT(0);
        }
        __syncthreads();   // stage nt visible to all threads

        const uint32_t wb = su + OFF_W + (nt % 3) * W_STAGE;

        // ---- fully unrolled chunk loop: Ar stays in registers ----
#pragma unroll
        for (int ch = 0; ch < 8; ++ch) {
            uint32_t p0, p1, p2, p3;       // ct0, w0 split
            uint32_t q0, q1, q2, q3;       // ct0, w1 split
            uint32_t r0, r1, r2, r3;       // ct1, w0 split
            uint32_t s0, s1, s2, s3;       // ct1, w1 split
            LDSM_X4(p0, p1, p2, p3, wb + 0 * W_SPLIT + ch * 2048 + boff[0]);
            LDSM_X4(q0, q1, q2, q3, wb + 1 * W_SPLIT + ch * 2048 + boff[0]);
            LDSM_X4(r0, r1, r2, r3, wb + 0 * W_SPLIT + ch * 2048 + boff[1]);
            LDSM_X4(s0, s1, s2, s3, wb + 1 * W_SPLIT + ch * 2048 + boff[1]);
#define A0_(i) Ar[ch * 8 + (i)]
#define A1_(i) Ar[ch * 8 + 4 + (i)]
            MMA16816(acc[0], A0_(0), A0_(1), A0_(2), A0_(3), p0, p1);
            MMA16816(acc[1], A0_(0), A0_(1), A0_(2), A0_(3), p2, p3);
            MMA16816(acc[2], A0_(0), A0_(1), A0_(2), A0_(3), r0, r1);
            MMA16816(acc[3], A0_(0), A0_(1), A0_(2), A0_(3), r2, r3);
            MMA16816(acc[0], A1_(0), A1_(1), A1_(2), A1_(3), p0, p1);
            MMA16816(acc[1], A1_(0), A1_(1), A1_(2), A1_(3), p2, p3);
            MMA16816(acc[2], A1_(0), A1_(1), A1_(2), A1_(3), r0, r1);
            MMA16816(acc[3], A1_(0), A1_(1), A1_(2), A1_(3), r2, r3);
            MMA16816(acc[0], A0_(0), A0_(1), A0_(2), A0_(3), q0, q1);
            MMA16816(acc[1], A0_(0), A0_(1), A0_(2), A0_(3), q2, q3);
            MMA16816(acc[2], A0_(0), A0_(1), A0_(2), A0_(3), s0, s1);
            MMA16816(acc[3], A0_(0), A0_(1), A0_(2), A0_(3), s2, s3);
#undef A0_
#undef A1_
        }

        // ---- stage epilogue: d2 + running argmin (ascending k) ----
        const int kq = nt * NSTAGE + chalf * 32 + (lane & 3) * 2;
#pragma unroll
        for (int t = 0; t < 4; ++t) {
            const int k0 = kq + t * 8;
#pragma unroll
            for (int q = 0; q < 2; ++q) {
                const int kk = k0 + q;
                const float e2v = e2s[kk];
                // acc holds xe*1024; -2*xe == (-2/1024)*acc, both scalings exact
                float tA = __fadd_rn(x2a, __fmul_rn(-0.001953125f, acc[t][q]));
                float dA = __fadd_rn(tA, e2v);
                if (dA < bdA) { bdA = dA; bkA = kk; }
                float tB = __fadd_rn(x2b, __fmul_rn(-0.001953125f, acc[t][q + 2]));
                float dB = __fadd_rn(tB, e2v);
                if (dB < bdB) { bdB = dB; bkB = kk; }
                acc[t][q] = 0.0f;
                acc[t][q + 2] = 0.0f;
            }
        }
    }

    // ---- merge across lanes/warps sharing a pixel ----
    {
        unsigned long long pA =
            ((unsigned long long)__float_as_uint(bdA) << 32) | (unsigned)bkA;
        unsigned long long pB =
            ((unsigned long long)__float_as_uint(bdB) << 32) | (unsigned)bkB;
        atomicMin(&best[px0 + (lane >> 2)], pA);
        atomicMin(&best[px0 + 8 + (lane >> 2)], pB);
    }
    __syncthreads();

    // ---- outputs: gather codebook rows + argmin ----
    const size_t obase = ((size_t)b * DCH) * HW + hw0;
    for (int t = tid; t < DCH * MTILE; t += NTHREADS) {
        int d = t >> 7;
        int px = t & 127;
        unsigned k = (unsigned)(best[px] & 0xFFFFFFFFu);
        out[obase + (size_t)d * HW + px] = w[(size_t)d * KCODES + k];
    }
    if (write_amin && tid < MTILE) {
        unsigned k = (unsigned)(best[tid] & 0xFFFFFFFFu);
        out[RES_ELEMS + (size_t)b * HW + hw0 + tid] = (float)k;
    }
}

extern "C" void kernel_launch(void* const* d_in, const int* in_sizes, int n_in,
                              void* d_out, int out_size) {
    const float* x = (const float*)d_in[0];
    const float* w = (const float*)d_in[1];
    float* out = (float*)d_out;
    const int write_amin = ((size_t)out_size > RES_ELEMS) ? 1 : 0;

    cudaFuncSetAttribute(nearest_embed_hmma_kernel,
                         cudaFuncAttributeMaxDynamicSharedMemorySize, SMEM_TOTAL);

    convert_w_kernel<<<NSTAGES, NSTAGE>>>(w);
    nearest_embed_hmma_kernel<<<(BATCH * HW) / MTILE, NTHREADS, SMEM_TOTAL>>>(
        x, w, out, write_amin);
}

// round 11
// speedup vs baseline: 1.3186x; 1.1280x over previous
#include <cuda_runtime.h>
#include <cuda_fp16.h>
#include <cstdint>

// NearestEmbed via mma.sync (HMMA) fp16 2-split GEMM + fused argmin.
// R11: M=64px CTAs, 256 threads, ~101KB smem -> 2 CTAs/SM so stage phases
//      (barrier/epilogue/LDSM bursts) of one CTA overlap MMA of the other.
//      Inner loop and arithmetic bit-identical to R10 (rel_err 0.0).
//   xe = x.w via 3 fp16 mma combos (x0w0, x0w1, x1w0), fp32 accum.
//   w scaled by 1024 (exact) before split; epilogue multiplies by -2/1024 (exact).
//   x2/e2: sequential fadd(rn(v*v)) ascending d; first-index tie-break.

#define DCH 128
#define KCODES 1024
#define HW 4096
#define BATCH 32
#define RES_ELEMS ((size_t)BATCH * DCH * HW)

#define NTHREADS 256
#define MTILE 64             // pixels per CTA
#define NSTAGE 64            // codes per stage
#define NSTAGES 16

#define A_SPLIT 16384        // one fp16 split of x tile: 8 chunks x 64px x 32B
#define W_SPLIT 16384        // one fp16 split of w stage: 8 chunks x 64c x 32B
#define W_STAGE (2 * W_SPLIT)   // 32768

#define OFF_A    0           // 2 x A_SPLIT = 32768
#define OFF_W    32768       // ring: 2 x W_STAGE = 65536
#define OFF_XF   32768       // overlay: x f32 tile [128d][64px] = 32768 (pre-loop)
#define OFF_E2   98304       // 1024 f32
#define OFF_X2   102400      // 64 f32
#define OFF_BEST 102656      // 64 u64
#define SMEM_TOTAL 103168    // x2 -> 206336 B/SM: two CTAs co-resident

__device__ __align__(16) unsigned char g_wsplit[NSTAGES * W_STAGE];
__device__ float g_e2[KCODES];

// ---------------- helpers ----------------
__device__ __forceinline__ uint32_t smem_u32(const void* p) {
    uint32_t a;
    asm("{ .reg .u64 t; cvta.to.shared.u64 t, %1; cvt.u32.u64 %0, t; }" : "=r"(a) : "l"(p));
    return a;
}
__device__ __forceinline__ void cp16(uint32_t dst, const void* src) {
    asm volatile("cp.async.cg.shared.global [%0], [%1], 16;" :: "r"(dst), "l"(src) : "memory");
}
#define CP_COMMIT() asm volatile("cp.async.commit_group;" ::: "memory")
#define CP_WAIT(N)  asm volatile("cp.async.wait_group %0;" :: "n"(N) : "memory")

#define LDSM_X4(R0, R1, R2, R3, ADDR) \
    asm volatile("ldmatrix.sync.aligned.m8n8.x4.shared.b16 {%0,%1,%2,%3}, [%4];" \
        : "=r"(R0), "=r"(R1), "=r"(R2), "=r"(R3) : "r"(ADDR))

#define MMA16816(D, A0r, A1r, A2r, A3r, B0, B1) \
    asm volatile("mma.sync.aligned.m16n8k16.row.col.f32.f16.f16.f32 " \
        "{%0,%1,%2,%3}, {%4,%5,%6,%7}, {%8,%9}, {%0,%1,%2,%3};" \
        : "+f"((D)[0]), "+f"((D)[1]), "+f"((D)[2]), "+f"((D)[3]) \
        : "r"(A0r), "r"(A1r), "r"(A2r), "r"(A3r), "r"(B0), "r"(B1))

// XOR-swizzled granule offset: row p (4 px/codes per 128B row), k-half h.
__device__ __host__ __forceinline__ uint32_t swz16(uint32_t p, uint32_t h) {
    uint32_t r = p >> 2;
    uint32_t col = (((p & 3u) * 2u + h) ^ (r & 7u));
    return r * 128u + col * 16u;
}

// exact fp32 -> fp16 hi/lo split (residual subtraction is exact: <=13 sig bits)
__device__ __forceinline__ void split2(float v, unsigned short& s0, unsigned short& s1) {
    __half h0 = __float2half_rn(v);
    float r = v - __half2float(h0);
    __half h1 = __float2half_rn(r);
    s0 = __half_as_ushort(h0);
    s1 = __half_as_ushort(h1);
}
__device__ __forceinline__ uint4 pack8(const unsigned short* s) {
    uint4 v;
    v.x = (uint32_t)s[0] | ((uint32_t)s[1] << 16);
    v.y = (uint32_t)s[2] | ((uint32_t)s[3] << 16);
    v.z = (uint32_t)s[4] | ((uint32_t)s[5] << 16);
    v.w = (uint32_t)s[6] | ((uint32_t)s[7] << 16);
    return v;
}

// ---------------- prep: e2 (exact) + scaled fp16 2-splits of w ----------------
__global__ void convert_w_kernel(const float* __restrict__ w) {
    const int nt = blockIdx.x;        // stage (64 codes)
    const int c = threadIdx.x;        // local code 0..63
    const int k = nt * NSTAGE + c;
    float e2 = 0.0f;
    for (int g = 0; g < 16; ++g) {    // granule g: d = 8g..8g+7 ascending
        unsigned short s0[8], s1[8];
#pragma unroll
        for (int j = 0; j < 8; ++j) {
            float v = w[(size_t)(g * 8 + j) * KCODES + k];
            e2 = __fadd_rn(e2, __fmul_rn(v, v));
            split2(v * 1024.0f, s0[j], s1[j]);   // exact scale by 2^10
        }
        const int ch = g >> 1, h = g & 1;
        unsigned char* base = g_wsplit + (size_t)nt * W_STAGE + (size_t)ch * 2048
                            + swz16((uint32_t)c, (uint32_t)h);
        *(uint4*)(base + 0 * W_SPLIT) = pack8(s0);
        *(uint4*)(base + 1 * W_SPLIT) = pack8(s1);
    }
    g_e2[k] = e2;
}

// ---------------- main ----------------
__global__ __launch_bounds__(NTHREADS, 2)
void nearest_embed_hmma_kernel(const float* __restrict__ x,
                               const float* __restrict__ w,
                               float* __restrict__ out,
                               int write_amin) {
    extern __shared__ char smem[];
    const uint32_t su = smem_u32(smem);
    const int tid = threadIdx.x;
    const int blk = blockIdx.x;
    const int b = blk >> 6;                    // 64 tiles of 64px per image
    const int hw0 = (blk & 63) * MTILE;

    float* e2s = (float*)(smem + OFF_E2);
    float* x2s = (float*)(smem + OFF_X2);
    unsigned long long* best = (unsigned long long*)(smem + OFF_BEST);

    if (tid < MTILE) best[tid] = 0xFFFFFFFFFFFFFFFFull;
    for (int i = tid; i < KCODES; i += NTHREADS) e2s[i] = g_e2[i];

    // ---- stage x f32 tile [128d][64px] into OFF_XF ----
    const float* xbase = x + ((size_t)b * DCH) * HW + hw0;
    for (int t = tid; t < DCH * 16; t += NTHREADS) {   // 16 granules per d-row
        int d = t >> 4, q = t & 15;
        cp16(su + OFF_XF + (uint32_t)(d * 256 + q * 16),
             xbase + (size_t)d * HW + q * 4);
    }
    CP_COMMIT();
    CP_WAIT(0);
    __syncthreads();

    // ---- x2 (exact sequential ascending d) ----
    const float* xf = (const float*)(smem + OFF_XF);
    if (tid < MTILE) {
        float a = 0.0f;
        for (int d = 0; d < DCH; ++d) {
            float v = xf[d * MTILE + tid];
            a = __fadd_rn(a, __fmul_rn(v, v));
        }
        x2s[tid] = a;
    }

    // ---- convert x tile -> 2 fp16 splits (swizzled A layout) ----
    {
        const int px = tid & 63;
        const int quarter = tid >> 6;        // 0..3 -> 4 granules each
        for (int g = quarter * 4; g < quarter * 4 + 4; ++g) {
            unsigned short s0[8], s1[8];
#pragma unroll
            for (int j = 0; j < 8; ++j)
                split2(xf[(g * 8 + j) * MTILE + px], s0[j], s1[j]);
            const int ch = g >> 1, h = g & 1;
            const uint32_t off = (uint32_t)(ch * 2048) + swz16((uint32_t)px, (uint32_t)h);
            *(uint4*)(smem + OFF_A + 0 * A_SPLIT + off) = pack8(s0);
            *(uint4*)(smem + OFF_A + 1 * A_SPLIT + off) = pack8(s1);
        }
    }
    __syncthreads();   // A ready; XF area (= W ring) now reusable

    // ---- prefetch w stages 0 and 1 ----
    for (int s = 0; s < 2; ++s) {
        const unsigned char* src = g_wsplit + (size_t)s * W_STAGE;
        const uint32_t dst = su + OFF_W + s * W_STAGE;
        for (int t = tid; t < W_STAGE / 16; t += NTHREADS)
            cp16(dst + (uint32_t)(t * 16), src + (size_t)t * 16);
        CP_COMMIT();
    }

    // ---- per-thread fragment addressing ----
    const int lane = tid & 31;
    const int warp = tid >> 5;          // 8 warps: 4 px-groups x 2 code-halves
    const int pg = warp >> 1;
    const int chalf = warp & 1;
    const int px0 = pg * 16;

    const uint32_t ap = (uint32_t)(px0 + (lane & 7) + ((lane >> 3) & 1) * 8);
    const uint32_t ah = (uint32_t)(lane >> 4);
    const uint32_t aoff = swz16(ap, ah);
    const uint32_t bc = (uint32_t)((lane & 7) + ((lane >> 4) & 1) * 8);
    const uint32_t bh = (uint32_t)((lane >> 3) & 1);
    uint32_t boff[2];
#pragma unroll
    for (int ct = 0; ct < 2; ++ct)
        boff[ct] = swz16((uint32_t)(chalf * 32 + ct * 16) + bc, bh);

    // ---- hoist ALL A fragments into registers (compile-time indices only) ----
    uint32_t Ar[64];    // [chunk*8 + split*4 + reg]
#pragma unroll
    for (int ch = 0; ch < 8; ++ch) {
        LDSM_X4(Ar[ch * 8 + 0], Ar[ch * 8 + 1], Ar[ch * 8 + 2], Ar[ch * 8 + 3],
                su + OFF_A + 0 * A_SPLIT + ch * 2048 + aoff);
        LDSM_X4(Ar[ch * 8 + 4], Ar[ch * 8 + 5], Ar[ch * 8 + 6], Ar[ch * 8 + 7],
                su + OFF_A + 1 * A_SPLIT + ch * 2048 + aoff);
    }

    const float x2a = x2s[px0 + (lane >> 2)];
    const float x2b = x2s[px0 + 8 + (lane >> 2)];

    float acc[4][4];
#pragma unroll
    for (int t = 0; t < 4; ++t)
#pragma unroll
        for (int q = 0; q < 4; ++q) acc[t][q] = 0.0f;

    float bdA = __int_as_float(0x7F800000), bdB = bdA;
    int bkA = 0, bkB = 0;

    for (int nt = 0; nt < NSTAGES; ++nt) {
        if (nt < NSTAGES - 1) { CP_WAIT(1); } else { CP_WAIT(0); }
        __syncthreads();   // stage nt visible to all threads

        const uint32_t wb = su + OFF_W + (nt & 1) * W_STAGE;

        // ---- fully unrolled chunk loop: Ar stays in registers ----
#pragma unroll
        for (int ch = 0; ch < 8; ++ch) {
            uint32_t p0, p1, p2, p3;       // ct0, w0 split
            uint32_t q0, q1, q2, q3;       // ct0, w1 split
            uint32_t r0, r1, r2, r3;       // ct1, w0 split
            uint32_t s0, s1, s2, s3;       // ct1, w1 split
            LDSM_X4(p0, p1, p2, p3, wb + 0 * W_SPLIT + ch * 2048 + boff[0]);
            LDSM_X4(q0, q1, q2, q3, wb + 1 * W_SPLIT + ch * 2048 + boff[0]);
            LDSM_X4(r0, r1, r2, r3, wb + 0 * W_SPLIT + ch * 2048 + boff[1]);
            LDSM_X4(s0, s1, s2, s3, wb + 1 * W_SPLIT + ch * 2048 + boff[1]);
#define A0_(i) Ar[ch * 8 + (i)]
#define A1_(i) Ar[ch * 8 + 4 + (i)]
            MMA16816(acc[0], A0_(0), A0_(1), A0_(2), A0_(3), p0, p1);
            MMA16816(acc[1], A0_(0), A0_(1), A0_(2), A0_(3), p2, p3);
            MMA16816(acc[2], A0_(0), A0_(1), A0_(2), A0_(3), r0, r1);
            MMA16816(acc[3], A0_(0), A0_(1), A0_(2), A0_(3), r2, r3);
            MMA16816(acc[0], A1_(0), A1_(1), A1_(2), A1_(3), p0, p1);
            MMA16816(acc[1], A1_(0), A1_(1), A1_(2), A1_(3), p2, p3);
            MMA16816(acc[2], A1_(0), A1_(1), A1_(2), A1_(3), r0, r1);
            MMA16816(acc[3], A1_(0), A1_(1), A1_(2), A1_(3), r2, r3);
            MMA16816(acc[0], A0_(0), A0_(1), A0_(2), A0_(3), q0, q1);
            MMA16816(acc[1], A0_(0), A0_(1), A0_(2), A0_(3), q2, q3);
            MMA16816(acc[2], A0_(0), A0_(1), A0_(2), A0_(3), s0, s1);
            MMA16816(acc[3], A0_(0), A0_(1), A0_(2), A0_(3), s2, s3);
#undef A0_
#undef A1_
        }

        __syncthreads();   // all reads of ring slot nt&1 done

        // ---- prefetch stage nt+2 into slot nt&1 (overlaps epilogue) ----
        if (nt + 2 < NSTAGES) {
            const unsigned char* src = g_wsplit + (size_t)(nt + 2) * W_STAGE;
            const uint32_t dst = su + OFF_W + (nt & 1) * W_STAGE;
            for (int t = tid; t < W_STAGE / 16; t += NTHREADS)
                cp16(dst + (uint32_t)(t * 16), src + (size_t)t * 16);
            CP_COMMIT();
        }

        // ---- stage epilogue: d2 + running argmin (ascending k) ----
        const int kq = nt * NSTAGE + chalf * 32 + (lane & 3) * 2;
#pragma unroll
        for (int t = 0; t < 4; ++t) {
            const int k0 = kq + t * 8;
#pragma unroll
            for (int q = 0; q < 2; ++q) {
                const int kk = k0 + q;
                const float e2v = e2s[kk];
                // acc holds xe*1024; -2*xe == (-2/1024)*acc, both scalings exact
                float tA = __fadd_rn(x2a, __fmul_rn(-0.001953125f, acc[t][q]));
                float dA = __fadd_rn(tA, e2v);
                if (dA < bdA) { bdA = dA; bkA = kk; }
                float tB = __fadd_rn(x2b, __fmul_rn(-0.001953125f, acc[t][q + 2]));
                float dB = __fadd_rn(tB, e2v);
                if (dB < bdB) { bdB = dB; bkB = kk; }
                acc[t][q] = 0.0f;
                acc[t][q + 2] = 0.0f;
            }
        }
    }

    // ---- merge across lanes/warps sharing a pixel ----
    {
        unsigned long long pA =
            ((unsigned long long)__float_as_uint(bdA) << 32) | (unsigned)bkA;
        unsigned long long pB =
            ((unsigned long long)__float_as_uint(bdB) << 32) | (unsigned)bkB;
        atomicMin(&best[px0 + (lane >> 2)], pA);
        atomicMin(&best[px0 + 8 + (lane >> 2)], pB);
    }
    __syncthreads();

    // ---- outputs: gather codebook rows + argmin ----
    const size_t obase = ((size_t)b * DCH) * HW + hw0;
    for (int t = tid; t < DCH * MTILE; t += NTHREADS) {
        int d = t >> 6;
        int px = t & 63;
        unsigned k = (unsigned)(best[px] & 0xFFFFFFFFu);
        out[obase + (size_t)d * HW + px] = w[(size_t)d * KCODES + k];
    }
    if (write_amin && tid < MTILE) {
        unsigned k = (unsigned)(best[tid] & 0xFFFFFFFFu);
        out[RES_ELEMS + (size_t)b * HW + hw0 + tid] = (float)k;
    }
}

extern "C" void kernel_launch(void* const* d_in, const int* in_sizes, int n_in,
                              void* d_out, int out_size) {
    const float* x = (const float*)d_in[0];
    const float* w = (const float*)d_in[1];
    float* out = (float*)d_out;
    const int write_amin = ((size_t)out_size > RES_ELEMS) ? 1 : 0;

    cudaFuncSetAttribute(nearest_embed_hmma_kernel,
                         cudaFuncAttributeMaxDynamicSharedMemorySize, SMEM_TOTAL);

    convert_w_kernel<<<NSTAGES, NSTAGE>>>(w);
    nearest_embed_hmma_kernel<<<(BATCH * HW) / MTILE, NTHREADS, SMEM_TOTAL>>>(
        x, w, out, write_amin);
}

// round 12
// speedup vs baseline: 1.3297x; 1.0084x over previous
#include <cuda_runtime.h>
#include <cuda_fp16.h>
#include <cstdint>

// NearestEmbed via mma.sync (HMMA) fp16 2-split GEMM + fused argmin.
// R12: single __syncthreads per stage (distance-1 prefetch into the slot last
//      read two stages ago, protected by the top-of-stage barrier).
//      Arithmetic bit-identical to R11 (rel_err 0.0).
//   xe = x.w via 3 fp16 mma combos (x0w0, x0w1, x1w0), fp32 accum.
//   w scaled by 1024 (exact) before split; epilogue multiplies by -2/1024 (exact).
//   x2/e2: sequential fadd(rn(v*v)) ascending d; first-index tie-break.

#define DCH 128
#define KCODES 1024
#define HW 4096
#define BATCH 32
#define RES_ELEMS ((size_t)BATCH * DCH * HW)

#define NTHREADS 256
#define MTILE 64             // pixels per CTA
#define NSTAGE 64            // codes per stage
#define NSTAGES 16

#define A_SPLIT 16384        // one fp16 split of x tile: 8 chunks x 64px x 32B
#define W_SPLIT 16384        // one fp16 split of w stage: 8 chunks x 64c x 32B
#define W_STAGE (2 * W_SPLIT)   // 32768

#define OFF_A    0           // 2 x A_SPLIT = 32768
#define OFF_W    32768       // ring: 2 x W_STAGE = 65536
#define OFF_XF   32768       // overlay: x f32 tile [128d][64px] = 32768 (pre-loop)
#define OFF_E2   98304       // 1024 f32
#define OFF_X2   102400      // 64 f32
#define OFF_BEST 102656      // 64 u64
#define SMEM_TOTAL 103168    // x2 -> 206336 B/SM: two CTAs co-resident

__device__ __align__(16) unsigned char g_wsplit[NSTAGES * W_STAGE];
__device__ float g_e2[KCODES];

// ---------------- helpers ----------------
__device__ __forceinline__ uint32_t smem_u32(const void* p) {
    uint32_t a;
    asm("{ .reg .u64 t; cvta.to.shared.u64 t, %1; cvt.u32.u64 %0, t; }" : "=r"(a) : "l"(p));
    return a;
}
__device__ __forceinline__ void cp16(uint32_t dst, const void* src) {
    asm volatile("cp.async.cg.shared.global [%0], [%1], 16;" :: "r"(dst), "l"(src) : "memory");
}
#define CP_COMMIT() asm volatile("cp.async.commit_group;" ::: "memory")
#define CP_WAIT(N)  asm volatile("cp.async.wait_group %0;" :: "n"(N) : "memory")

#define LDSM_X4(R0, R1, R2, R3, ADDR) \
    asm volatile("ldmatrix.sync.aligned.m8n8.x4.shared.b16 {%0,%1,%2,%3}, [%4];" \
        : "=r"(R0), "=r"(R1), "=r"(R2), "=r"(R3) : "r"(ADDR))

#define MMA16816(D, A0r, A1r, A2r, A3r, B0, B1) \
    asm volatile("mma.sync.aligned.m16n8k16.row.col.f32.f16.f16.f32 " \
        "{%0,%1,%2,%3}, {%4,%5,%6,%7}, {%8,%9}, {%0,%1,%2,%3};" \
        : "+f"((D)[0]), "+f"((D)[1]), "+f"((D)[2]), "+f"((D)[3]) \
        : "r"(A0r), "r"(A1r), "r"(A2r), "r"(A3r), "r"(B0), "r"(B1))

// XOR-swizzled granule offset: row p (4 px/codes per 128B row), k-half h.
__device__ __host__ __forceinline__ uint32_t swz16(uint32_t p, uint32_t h) {
    uint32_t r = p >> 2;
    uint32_t col = (((p & 3u) * 2u + h) ^ (r & 7u));
    return r * 128u + col * 16u;
}

// exact fp32 -> fp16 hi/lo split (residual subtraction is exact: <=13 sig bits)
__device__ __forceinline__ void split2(float v, unsigned short& s0, unsigned short& s1) {
    __half h0 = __float2half_rn(v);
    float r = v - __half2float(h0);
    __half h1 = __float2half_rn(r);
    s0 = __half_as_ushort(h0);
    s1 = __half_as_ushort(h1);
}
__device__ __forceinline__ uint4 pack8(const unsigned short* s) {
    uint4 v;
    v.x = (uint32_t)s[0] | ((uint32_t)s[1] << 16);
    v.y = (uint32_t)s[2] | ((uint32_t)s[3] << 16);
    v.z = (uint32_t)s[4] | ((uint32_t)s[5] << 16);
    v.w = (uint32_t)s[6] | ((uint32_t)s[7] << 16);
    return v;
}

// ---------------- prep: e2 (exact) + scaled fp16 2-splits of w ----------------
__global__ void convert_w_kernel(const float* __restrict__ w) {
    const int nt = blockIdx.x;        // stage (64 codes)
    const int c = threadIdx.x;        // local code 0..63
    const int k = nt * NSTAGE + c;
    float e2 = 0.0f;
    for (int g = 0; g < 16; ++g) {    // granule g: d = 8g..8g+7 ascending
        unsigned short s0[8], s1[8];
#pragma unroll
        for (int j = 0; j < 8; ++j) {
            float v = w[(size_t)(g * 8 + j) * KCODES + k];
            e2 = __fadd_rn(e2, __fmul_rn(v, v));
            split2(v * 1024.0f, s0[j], s1[j]);   // exact scale by 2^10
        }
        const int ch = g >> 1, h = g & 1;
        unsigned char* base = g_wsplit + (size_t)nt * W_STAGE + (size_t)ch * 2048
                            + swz16((uint32_t)c, (uint32_t)h);
        *(uint4*)(base + 0 * W_SPLIT) = pack8(s0);
        *(uint4*)(base + 1 * W_SPLIT) = pack8(s1);
    }
    g_e2[k] = e2;
}

// ---------------- main ----------------
__global__ __launch_bounds__(NTHREADS, 2)
void nearest_embed_hmma_kernel(const float* __restrict__ x,
                               const float* __restrict__ w,
                               float* __restrict__ out,
                               int write_amin) {
    extern __shared__ char smem[];
    const uint32_t su = smem_u32(smem);
    const int tid = threadIdx.x;
    const int blk = blockIdx.x;
    const int b = blk >> 6;                    // 64 tiles of 64px per image
    const int hw0 = (blk & 63) * MTILE;

    float* e2s = (float*)(smem + OFF_E2);
    float* x2s = (float*)(smem + OFF_X2);
    unsigned long long* best = (unsigned long long*)(smem + OFF_BEST);

    if (tid < MTILE) best[tid] = 0xFFFFFFFFFFFFFFFFull;
    for (int i = tid; i < KCODES; i += NTHREADS) e2s[i] = g_e2[i];

    // ---- stage x f32 tile [128d][64px] into OFF_XF ----
    const float* xbase = x + ((size_t)b * DCH) * HW + hw0;
    for (int t = tid; t < DCH * 16; t += NTHREADS) {   // 16 granules per d-row
        int d = t >> 4, q = t & 15;
        cp16(su + OFF_XF + (uint32_t)(d * 256 + q * 16),
             xbase + (size_t)d * HW + q * 4);
    }
    CP_COMMIT();
    CP_WAIT(0);
    __syncthreads();

    // ---- x2 (exact sequential ascending d) ----
    const float* xf = (const float*)(smem + OFF_XF);
    if (tid < MTILE) {
        float a = 0.0f;
        for (int d = 0; d < DCH; ++d) {
            float v = xf[d * MTILE + tid];
            a = __fadd_rn(a, __fmul_rn(v, v));
        }
        x2s[tid] = a;
    }

    // ---- convert x tile -> 2 fp16 splits (swizzled A layout) ----
    {
        const int px = tid & 63;
        const int quarter = tid >> 6;        // 0..3 -> 4 granules each
        for (int g = quarter * 4; g < quarter * 4 + 4; ++g) {
            unsigned short s0[8], s1[8];
#pragma unroll
            for (int j = 0; j < 8; ++j)
                split2(xf[(g * 8 + j) * MTILE + px], s0[j], s1[j]);
            const int ch = g >> 1, h = g & 1;
            const uint32_t off = (uint32_t)(ch * 2048) + swz16((uint32_t)px, (uint32_t)h);
            *(uint4*)(smem + OFF_A + 0 * A_SPLIT + off) = pack8(s0);
            *(uint4*)(smem + OFF_A + 1 * A_SPLIT + off) = pack8(s1);
        }
    }
    __syncthreads();   // A ready; XF area (= W ring) now reusable

    // ---- prefetch w stage 0 ----
    {
        const unsigned char* src = g_wsplit;
        const uint32_t dst = su + OFF_W;
        for (int t = tid; t < W_STAGE / 16; t += NTHREADS)
            cp16(dst + (uint32_t)(t * 16), src + (size_t)t * 16);
        CP_COMMIT();
    }

    // ---- per-thread fragment addressing ----
    const int lane = tid & 31;
    const int warp = tid >> 5;          // 8 warps: 4 px-groups x 2 code-halves
    const int pg = warp >> 1;
    const int chalf = warp & 1;
    const int px0 = pg * 16;

    const uint32_t ap = (uint32_t)(px0 + (lane & 7) + ((lane >> 3) & 1) * 8);
    const uint32_t ah = (uint32_t)(lane >> 4);
    const uint32_t aoff = swz16(ap, ah);
    const uint32_t bc = (uint32_t)((lane & 7) + ((lane >> 4) & 1) * 8);
    const uint32_t bh = (uint32_t)((lane >> 3) & 1);
    uint32_t boff[2];
#pragma unroll
    for (int ct = 0; ct < 2; ++ct)
        boff[ct] = swz16((uint32_t)(chalf * 32 + ct * 16) + bc, bh);

    // ---- hoist ALL A fragments into registers (compile-time indices only) ----
    uint32_t Ar[64];    // [chunk*8 + split*4 + reg]
#pragma unroll
    for (int ch = 0; ch < 8; ++ch) {
        LDSM_X4(Ar[ch * 8 + 0], Ar[ch * 8 + 1], Ar[ch * 8 + 2], Ar[ch * 8 + 3],
                su + OFF_A + 0 * A_SPLIT + ch * 2048 + aoff);
        LDSM_X4(Ar[ch * 8 + 4], Ar[ch * 8 + 5], Ar[ch * 8 + 6], Ar[ch * 8 + 7],
                su + OFF_A + 1 * A_SPLIT + ch * 2048 + aoff);
    }

    const float x2a = x2s[px0 + (lane >> 2)];
    const float x2b = x2s[px0 + 8 + (lane >> 2)];

    float acc[4][4];
#pragma unroll
    for (int t = 0; t < 4; ++t)
#pragma unroll
        for (int q = 0; q < 4; ++q) acc[t][q] = 0.0f;

    float bdA = __int_as_float(0x7F800000), bdB = bdA;
    int bkA = 0, bkB = 0;

    for (int nt = 0; nt < NSTAGES; ++nt) {
        // stage nt's data was the most recent cp.async group -> wait all
        CP_WAIT(0);
        // single barrier: stage nt visible to all threads, AND all threads are
        // done reading slot (nt+1)&1 (their stage nt-1 compute is complete)
        __syncthreads();

        // ---- prefetch stage nt+1 into slot (nt+1)&1, overlapping compute ----
        if (nt + 1 < NSTAGES) {
            const unsigned char* src = g_wsplit + (size_t)(nt + 1) * W_STAGE;
            const uint32_t dst = su + OFF_W + ((nt + 1) & 1) * W_STAGE;
            for (int t = tid; t < W_STAGE / 16; t += NTHREADS)
                cp16(dst + (uint32_t)(t * 16), src + (size_t)t * 16);
            CP_COMMIT();
        }

        const uint32_t wb = su + OFF_W + (nt & 1) * W_STAGE;

        // ---- fully unrolled chunk loop: Ar stays in registers ----
#pragma unroll
        for (int ch = 0; ch < 8; ++ch) {
            uint32_t p0, p1, p2, p3;       // ct0, w0 split
            uint32_t q0, q1, q2, q3;       // ct0, w1 split
            uint32_t r0, r1, r2, r3;       // ct1, w0 split
            uint32_t s0, s1, s2, s3;       // ct1, w1 split
            LDSM_X4(p0, p1, p2, p3, wb + 0 * W_SPLIT + ch * 2048 + boff[0]);
            LDSM_X4(q0, q1, q2, q3, wb + 1 * W_SPLIT + ch * 2048 + boff[0]);
            LDSM_X4(r0, r1, r2, r3, wb + 0 * W_SPLIT + ch * 2048 + boff[1]);
            LDSM_X4(s0, s1, s2, s3, wb + 1 * W_SPLIT + ch * 2048 + boff[1]);
#define A0_(i) Ar[ch * 8 + (i)]
#define A1_(i) Ar[ch * 8 + 4 + (i)]
            MMA16816(acc[0], A0_(0), A0_(1), A0_(2), A0_(3), p0, p1);
            MMA16816(acc[1], A0_(0), A0_(1), A0_(2), A0_(3), p2, p3);
            MMA16816(acc[2], A0_(0), A0_(1), A0_(2), A0_(3), r0, r1);
            MMA16816(acc[3], A0_(0), A0_(1), A0_(2), A0_(3), r2, r3);
            MMA16816(acc[0], A1_(0), A1_(1), A1_(2), A1_(3), p0, p1);
            MMA16816(acc[1], A1_(0), A1_(1), A1_(2), A1_(3), p2, p3);
            MMA16816(acc[2], A1_(0), A1_(1), A1_(2), A1_(3), r0, r1);
            MMA16816(acc[3], A1_(0), A1_(1), A1_(2), A1_(3), r2, r3);
            MMA16816(acc[0], A0_(0), A0_(1), A0_(2), A0_(3), q0, q1);
            MMA16816(acc[1], A0_(0), A0_(1), A0_(2), A0_(3), q2, q3);
            MMA16816(acc[2], A0_(0), A0_(1), A0_(2), A0_(3), s0, s1);
            MMA16816(acc[3], A0_(0), A0_(1), A0_(2), A0_(3), s2, s3);
#undef A0_
#undef A1_
        }

        // ---- stage epilogue: d2 + running argmin (ascending k) ----
        const int kq = nt * NSTAGE + chalf * 32 + (lane & 3) * 2;
#pragma unroll
        for (int t = 0; t < 4; ++t) {
            const int k0 = kq + t * 8;
#pragma unroll
            for (int q = 0; q < 2; ++q) {
                const int kk = k0 + q;
                const float e2v = e2s[kk];
                // acc holds xe*1024; -2*xe == (-2/1024)*acc, both scalings exact
                float tA = __fadd_rn(x2a, __fmul_rn(-0.001953125f, acc[t][q]));
                float dA = __fadd_rn(tA, e2v);
                if (dA < bdA) { bdA = dA; bkA = kk; }
                float tB = __fadd_rn(x2b, __fmul_rn(-0.001953125f, acc[t][q + 2]));
                float dB = __fadd_rn(tB, e2v);
                if (dB < bdB) { bdB = dB; bkB = kk; }
                acc[t][q] = 0.0f;
                acc[t][q + 2] = 0.0f;
            }
        }
    }

    // ---- merge across lanes/warps sharing a pixel ----
    {
        unsigned long long pA =
            ((unsigned long long)__float_as_uint(bdA) << 32) | (unsigned)bkA;
        unsigned long long pB =
            ((unsigned long long)__float_as_uint(bdB) << 32) | (unsigned)bkB;
        atomicMin(&best[px0 + (lane >> 2)], pA);
        atomicMin(&best[px0 + 8 + (lane >> 2)], pB);
    }
    __syncthreads();

    // ---- outputs: gather codebook rows + argmin ----
    const size_t obase = ((size_t)b * DCH) * HW + hw0;
    for (int t = tid; t < DCH * MTILE; t += NTHREADS) {
        int d = t >> 6;
        int px = t & 63;
        unsigned k = (unsigned)(best[px] & 0xFFFFFFFFu);
        out[obase + (size_t)d * HW + px] = w[(size_t)d * KCODES + k];
    }
    if (write_amin && tid < MTILE) {
        unsigned k = (unsigned)(best[tid] & 0xFFFFFFFFu);
        out[RES_ELEMS + (size_t)b * HW + hw0 + tid] = (float)k;
    }
}

extern "C" void kernel_launch(void* const* d_in, const int* in_sizes, int n_in,
                              void* d_out, int out_size) {
    const float* x = (const float*)d_in[0];
    const float* w = (const float*)d_in[1];
    float* out = (float*)d_out;
    const int write_amin = ((size_t)out_size > RES_ELEMS) ? 1 : 0;

    cudaFuncSetAttribute(nearest_embed_hmma_kernel,
                         cudaFuncAttributeMaxDynamicSharedMemorySize, SMEM_TOTAL);

    convert_w_kernel<<<NSTAGES, NSTAGE>>>(w);
    nearest_embed_hmma_kernel<<<(BATCH * HW) / MTILE, NTHREADS, SMEM_TOTAL>>>(
        x, w, out, write_amin);
}